// round 1
// baseline (speedup 1.0000x reference)
#include <cuda_runtime.h>

// 16-qubit, 2-layer BasicEntangler circuit, batch 32.
//
// Algebraic reduction:
//   |psi> = P * RX(W1) * P * RX(W0) * RX(x) |0>,  P = CNOT ring (linear GF(2) map F)
//         = P^2 * R1' * |A>
//   |A>  = product state with per-wire angle phi_w = x_w + W0_w
//   R1'  = prod_v exp(-i W1_v/2 * X_{b_v}),  b_v = F^{-1} e_v
//          b_0={0,1}, b_v={v,v+1} (v=1..14), b_15={0,1,15}
//   <Z_w> = sum_t |(R1'|A>)[t]|^2 * (-1)^{parity(R_w & t)}, R_w = row w of F^2
//
// Kernel 1: build |A> tile (bits 0..11 local), apply rotations b_0..b_10, store.
// Kernel 2: retile (bits {0..6,11..15} local), apply b_11..b_15, fused measurement.

#define NQ      16
#define NSTATE  65536
#define BATCH   32
#define TILE_BITS 12
#define TILE    (1 << TILE_BITS)
#define THREADS 256

__device__ float2 g_state[BATCH * NSTATE];   // 16 MB scratch (static, allowed)

// R_w = row w of F^2, as wire-bit masks (bit w of index = wire w value)
__constant__ unsigned int R_MASK[16] = {
    0xAAABu, 0xFFFDu, 0xFFFAu, 0xFFF5u, 0xFFEAu, 0xFFD5u, 0xFFAAu, 0xFF55u,
    0xFEAAu, 0xFD55u, 0xFAAAu, 0xF555u, 0xEAAAu, 0xD555u, 0xAAAAu, 0x5555u
};

// Apply exp(-i*theta/2 * X_mask) on pair (a, b): a' = c*a - i*s*b ; b' = c*b - i*s*a
__device__ __forceinline__ void rot_pair(float2& a, float2& b, float c, float s) {
    float2 na, nb;
    na.x = c * a.x + s * b.y;
    na.y = c * a.y - s * b.x;
    nb.x = c * b.x + s * a.y;
    nb.y = c * b.y - s * a.x;
    a = na; b = nb;
}

__global__ void __launch_bounds__(THREADS)
qnn_k1(const float* __restrict__ x, const float* __restrict__ wts) {
    __shared__ float2 tile[TILE];
    __shared__ float cw[NQ], sw[NQ];
    __shared__ float rc[11], rs[11];

    const int outer = blockIdx.x;   // bits 12..15
    const int b     = blockIdx.y;   // sample
    const int tid   = threadIdx.x;

    if (tid < NQ) {
        float phi = x[b * NQ + tid] + wts[tid];   // embedding + layer-0 fused
        cw[tid] = cosf(0.5f * phi);
        sw[tid] = sinf(0.5f * phi);
    }
    if (tid >= 32 && tid < 32 + 11) {
        int v = tid - 32;
        float th = 0.5f * wts[NQ + v];            // layer-1 weights
        rc[v] = cosf(th);
        rs[v] = sinf(th);
    }
    __syncthreads();

    // Product-state init: amp[t] = prod_w (t_w ? -i*s_w : c_w)
    for (int l = tid; l < TILE; l += THREADS) {
        int t = (outer << TILE_BITS) | l;
        float mag = 1.0f;
#pragma unroll
        for (int w = 0; w < NQ; w++)
            mag *= ((t >> w) & 1) ? sw[w] : cw[w];
        int k = __popc((unsigned)t) & 3;          // phase (-i)^k
        float2 a;
        a.x = (k == 0) ? mag : ((k == 2) ? -mag : 0.0f);
        a.y = (k == 1) ? -mag : ((k == 3) ? mag : 0.0f);
        tile[l] = a;
    }
    __syncthreads();

    // Rotations on masks {v, v+1}, v = 0..10 (all within bits 0..11)
    for (int v = 0; v < 11; v++) {
        const float c = rc[v], s = rs[v];
        const int m  = 3 << v;
        const int hb = 1 << (v + 1);              // highest bit of mask
        for (int i = tid; i < TILE / 2; i += THREADS) {
            int l = ((i & ~(hb - 1)) << 1) | (i & (hb - 1));  // bit hb == 0
            int p = l ^ m;
            float2 a = tile[l], bb = tile[p];
            rot_pair(a, bb, c, s);
            tile[l] = a; tile[p] = bb;
        }
        __syncthreads();
    }

    float2* dst = g_state + b * NSTATE + (outer << TILE_BITS);
    for (int l = tid; l < TILE; l += THREADS) dst[l] = tile[l];
}

__global__ void __launch_bounds__(THREADS)
qnn_k2(const float* __restrict__ wts, float* __restrict__ out) {
    __shared__ float2 tile[TILE];
    __shared__ float rc[5], rs[5];
    __shared__ float racc[8][16];

    const int outer = blockIdx.x;   // bits 7..10
    const int b     = blockIdx.y;
    const int tid   = threadIdx.x;

    // local bits: [0..6] -> global 0..6, [7..11] -> global 11..15
    for (int l = tid; l < TILE; l += THREADS) {
        int t = (l & 0x7F) | (outer << 7) | ((l >> 7) << 11);
        tile[l] = g_state[b * NSTATE + t];
    }
    if (tid < 5) {
        float th = 0.5f * wts[NQ + 11 + tid];
        rc[tid] = cosf(th);
        rs[tid] = sinf(th);
    }
    __syncthreads();

    // local masks for b_11..b_15: {11,12},{12,13},{13,14},{14,15},{0,1,15}
    const int masks[5] = {0x180, 0x300, 0x600, 0xC00, 0x803};
    const int hbs[5]   = {0x100, 0x200, 0x400, 0x800, 0x800};
#pragma unroll
    for (int v = 0; v < 5; v++) {
        const float c = rc[v], s = rs[v];
        const int m = masks[v], hb = hbs[v];
        for (int i = tid; i < TILE / 2; i += THREADS) {
            int l = ((i & ~(hb - 1)) << 1) | (i & (hb - 1));
            int p = l ^ m;
            float2 a = tile[l], bb = tile[p];
            rot_pair(a, bb, c, s);
            tile[l] = a; tile[p] = bb;
        }
        __syncthreads();
    }

    // Fused measurement: acc[w] += |amp|^2 * (-1)^{parity(t & R_w)}
    float acc[16];
#pragma unroll
    for (int w = 0; w < 16; w++) acc[w] = 0.0f;

    for (int l = tid; l < TILE; l += THREADS) {
        int t = (l & 0x7F) | (outer << 7) | ((l >> 7) << 11);
        float2 a = tile[l];
        float p = a.x * a.x + a.y * a.y;
#pragma unroll
        for (int w = 0; w < 16; w++)
            acc[w] += (__popc((unsigned)t & R_MASK[w]) & 1) ? -p : p;
    }

    // warp reduce, then cross-warp via smem, then atomics to out
#pragma unroll
    for (int w = 0; w < 16; w++) {
#pragma unroll
        for (int off = 16; off > 0; off >>= 1)
            acc[w] += __shfl_xor_sync(0xFFFFFFFFu, acc[w], off);
    }
    const int warp = tid >> 5, lane = tid & 31;
    if (lane == 0) {
#pragma unroll
        for (int w = 0; w < 16; w++) racc[warp][w] = acc[w];
    }
    __syncthreads();
    if (tid < 16) {
        float s = 0.0f;
#pragma unroll
        for (int q = 0; q < 8; q++) s += racc[q][tid];
        atomicAdd(&out[b * 16 + tid], s);
    }
}

extern "C" void kernel_launch(void* const* d_in, const int* in_sizes, int n_in,
                              void* d_out, int out_size) {
    const float* x   = (const float*)d_in[0];   // (32,16)
    const float* wts = (const float*)d_in[1];   // (2,16)
    if (n_in >= 2 && in_sizes[0] == 32 && in_sizes[1] == 512) {
        // defensive: swap if metadata order differs
        const float* tmp = x; x = wts; wts = tmp;
    }
    float* out = (float*)d_out;                 // (32,16) float32

    cudaMemsetAsync(out, 0, 32 * 16 * sizeof(float));

    dim3 grid(16, BATCH);
    qnn_k1<<<grid, THREADS>>>(x, wts);
    qnn_k2<<<grid, THREADS>>>(wts, out);
}

// round 2
// speedup vs baseline: 2.4391x; 2.4391x over previous
#include <cuda_runtime.h>

// 16-qubit, 2-layer BasicEntangler QNN — closed-form via commuting X-generators.
//
// |psi> = Prod_v exp(-i W1_v/2 X_{b_v}) * Prod_w exp(-i phi_w/2 X_w) |0>,
//         phi_w = x_w + W0_w,
//         b_0={0,1}, b_v={v,v+1} (v=1..14), b_15={0,1,15}   (= F^{-1} e_v)
// <Z_w> = <psi| Z_{R_w} |psi>,  R_w = row w of F^2  (verified masks, round 1)
//
// Since all generators are X-type (mutually commuting) and Z_S either commutes
// or anticommutes with each:
//   <Z_S> = <0| Prod_{j in A} exp(i theta_j X_{m_j}) |0>
//         = sum over subsets T of A with XOR(masks)=0 of
//              i^|T| * prod_{T} sin(theta) * prod_{A\T} cos(theta)
// where A = { j : popc(m_j & S) odd }, theta_j = full rotation angle.
//
// The b-chain structure makes this a 2-state transfer-matrix DP over bit
// positions w=0..15 (XOR-mask bit w = t_{w-1} ^ t_w, with t_15 feeding bits
// 0,1,15). One thread per (sample, output wire): 512 threads, one block.

#define BATCH 32
#define NQ    16

__constant__ unsigned int R_MASK[16] = {
    0xAAABu, 0xFFFDu, 0xFFFAu, 0xFFF5u, 0xFFEAu, 0xFFD5u, 0xFFAAu, 0xFF55u,
    0xFEAAu, 0xFD55u, 0xFAAAu, 0xF555u, 0xEAAAu, 0xD555u, 0xAAAAu, 0x5555u
};

__device__ __forceinline__ float2 cmul(float2 a, float2 b) {
    return make_float2(a.x * b.x - a.y * b.y, a.x * b.y + a.y * b.x);
}

__global__ void __launch_bounds__(BATCH * NQ)
qnn_tm(const float* __restrict__ x, const float* __restrict__ wts,
       float* __restrict__ out) {
    __shared__ float cphi[BATCH * NQ], sphi[BATCH * NQ];
    __shared__ float cth[NQ], sth[NQ];

    const int tid = threadIdx.x;

    // phi_w = x_w + W0_w  (embedding + layer-0 fused, full angle)
    {
        float phi = x[tid] + wts[tid & 15];
        float s, c;
        sincosf(phi, &s, &c);
        sphi[tid] = s; cphi[tid] = c;
    }
    if (tid < NQ) {
        float s, c;
        sincosf(wts[NQ + tid], &s, &c);   // layer-1 angles (full)
        sth[tid] = s; cth[tid] = c;
    }
    __syncthreads();

    const int b  = tid >> 4;
    const int wo = tid & 15;
    const unsigned S = R_MASK[wo];
    const float* cp = cphi + b * NQ;
    const float* sp = sphi + b * NQ;

    // A_b membership: b_v anticommutes with Z_S iff popc(b_v & S) odd
    bool ab[16];
    ab[0] = __popc(0x3u & S) & 1;
#pragma unroll
    for (int v = 1; v <= 14; v++) ab[v] = __popc((3u << v) & S) & 1;
    ab[15] = __popc(0x8003u & S) & 1;

    float2 total = make_float2(0.f, 0.f);

    const int t15max = ab[15] ? 1 : 0;
    for (int t15 = 0; t15 <= t15max; t15++) {
        const float2 w15 = ab[15]
            ? (t15 ? make_float2(0.f, sth[15]) : make_float2(cth[15], 0.f))
            : make_float2(1.f, 0.f);

        // DP state: amplitude indexed by t_{w-1} (previous chain variable)
        float2 amp0 = make_float2(0.f, 0.f);
        float2 amp1 = make_float2(0.f, 0.f);

        // step w = 0: choose t_0; mask bit 0 = t_0 ^ t_15
        {
            const bool ae = S & 1u;
            const int t0max = ab[0] ? 1 : 0;
            for (int t0 = 0; t0 <= t0max; t0++) {
                float2 wt = ab[0]
                    ? (t0 ? make_float2(0.f, sth[0]) : make_float2(cth[0], 0.f))
                    : make_float2(1.f, 0.f);
                const int M = t0 ^ t15;
                float2 wm;
                if (ae) wm = M ? make_float2(0.f, sp[0]) : make_float2(cp[0], 0.f);
                else { if (M) continue; wm = make_float2(1.f, 0.f); }
                float2 v = cmul(wt, wm);
                if (t0) amp1 = v; else amp0 = v;
            }
        }

        // steps w = 1..14: mask bit w = t_{w-1} ^ t_w  (^ t_15 at w==1)
        for (int w = 1; w <= 14; w++) {
            const bool ae = (S >> w) & 1u;
            float2 n0 = make_float2(0.f, 0.f);
            float2 n1 = make_float2(0.f, 0.f);
            const int twmax = ab[w] ? 1 : 0;
            for (int tw = 0; tw <= twmax; tw++) {
                float2 wt = ab[w]
                    ? (tw ? make_float2(0.f, sth[w]) : make_float2(cth[w], 0.f))
                    : make_float2(1.f, 0.f);
                for (int tp = 0; tp < 2; tp++) {
                    int M = tp ^ tw;
                    if (w == 1) M ^= t15;
                    float2 wm;
                    if (ae) wm = M ? make_float2(0.f, sp[w]) : make_float2(cp[w], 0.f);
                    else { if (M) continue; wm = make_float2(1.f, 0.f); }
                    float2 prev = tp ? amp1 : amp0;
                    float2 add = cmul(prev, cmul(wt, wm));
                    if (tw) { n1.x += add.x; n1.y += add.y; }
                    else    { n0.x += add.x; n0.y += add.y; }
                }
            }
            amp0 = n0; amp1 = n1;
        }

        // close the chain: mask bit 15 = t_14 ^ t_15
        {
            const bool ae = (S >> 15) & 1u;
            for (int tp = 0; tp < 2; tp++) {
                const int M = tp ^ t15;
                float2 wm;
                if (ae) wm = M ? make_float2(0.f, sp[15]) : make_float2(cp[15], 0.f);
                else { if (M) continue; wm = make_float2(1.f, 0.f); }
                float2 prev = tp ? amp1 : amp0;
                float2 v = cmul(cmul(prev, wm), w15);
                total.x += v.x; total.y += v.y;
            }
        }
    }

    out[tid] = total.x;   // result is real; imaginary parts cancel
}

extern "C" void kernel_launch(void* const* d_in, const int* in_sizes, int n_in,
                              void* d_out, int out_size) {
    const float* x   = (const float*)d_in[0];   // (32,16)
    const float* wts = (const float*)d_in[1];   // (2,16)
    if (n_in >= 2 && in_sizes[0] == 32 && in_sizes[1] == 512) {
        const float* tmp = x; x = wts; wts = tmp;  // defensive order swap
    }
    float* out = (float*)d_out;                 // (32,16) float32

    qnn_tm<<<1, BATCH * NQ>>>(x, wts, out);
}

// round 3
// speedup vs baseline: 6.7639x; 2.7731x over previous
#include <cuda_runtime.h>

// 16-qubit, 2-layer BasicEntangler QNN — branchless transfer-matrix closed form.
//
// <Z_{R_w}> = <0| Prod_{j in A} exp(i theta_j X_{m_j}) |0>
//  masks: m_w = {w} (angle phi_w = x_w + W0_w), b_0={0,1}, b_v={v,v+1},
//  b_15={0,1,15}; A-membership and the XOR(masks)=0 constraint reduce to a
//  2-state chain DP over wire index w, with chain variable t_w and an outer
//  variable t15 feeding mask bits {0,1,15}. Two chains (t15=0/1) run in
//  parallel, fully branchless (excluded options carry weight 0/1 via SEL).

#define NQ 16

__constant__ unsigned int R_MASK[16] = {
    0xAAABu, 0xFFFDu, 0xFFFAu, 0xFFF5u, 0xFFEAu, 0xFFD5u, 0xFFAAu, 0xFF55u,
    0xFEAAu, 0xFD55u, 0xFAAAu, 0xF555u, 0xEAAAu, 0xD555u, 0xAAAAu, 0x5555u
};

__global__ void __launch_bounds__(32)
qnn_tm2(const float* __restrict__ x, const float* __restrict__ wts,
        float* __restrict__ out) {
    __shared__ float cph[32], sph[32], cth[NQ], sth[NQ];

    const int tid = threadIdx.x;
    const int w   = tid & 15;                      // output wire
    const int b   = (blockIdx.x << 1) | (tid >> 4); // sample
    const int base = tid & 16;                     // smem offset of my sample

    float s, c;
    sincosf(x[b * NQ + w] + wts[w], &s, &c);       // phi = x + W0 (full angle)
    cph[tid] = c; sph[tid] = s;
    if (tid < NQ) {
        sincosf(wts[NQ + tid], &s, &c);            // layer-1 theta (full angle)
        cth[tid] = c; sth[tid] = s;
    }
    __syncthreads();

    const unsigned S = R_MASK[w];

    // chain A: t15 = 0; chain B: t15 = 1 (mask bits 0,1,15 get ^1)
    float a0x, a0y, a1x, a1y;
    float b0x, b0y, b1x, b1y;

    // ---- step w=0: amp_{t0} = wt(t0) * wm(t0 ^ t15) ----
    {
        const bool ab = (S ^ (S >> 1)) & 1;        // b_0={0,1} anticommutes?
        const bool ae = S & 1;
        const float wt0r = ab ? cth[0] : 1.f;
        const float wt1i = ab ? sth[0] : 0.f;
        const float wm0r = ae ? cph[base + 0] : 1.f;
        const float wm1i = ae ? sph[base + 0] : 0.f;
        a0x =  wt0r * wm0r;  a0y = 0.f;            // wt(0)*wm(0)
        a1x = -wt1i * wm1i;  a1y = 0.f;            // (i wt1i)*(i wm1i)
        b0x = 0.f;  b0y = wt0r * wm1i;             // wt(0)*wm(1)
        b1x = 0.f;  b1y = wt1i * wm0r;             // (i wt1i)*wm(0)
    }

    // ---- steps v=1..14: n_{tv} = wt(tv) * u_{tv [^1 if v==1 on chain B]}
    //      u_m = amp0*wm(m) + amp1*wm(1^m)
#pragma unroll
    for (int v = 1; v <= 14; v++) {
        const bool ab = ((S >> v) ^ (S >> (v + 1))) & 1;
        const bool ae = (S >> v) & 1;
        const float wt0r = ab ? cth[v] : 1.f;
        const float wt1i = ab ? sth[v] : 0.f;
        const float wm0r = ae ? cph[base + v] : 1.f;
        const float wm1i = ae ? sph[base + v] : 0.f;

        // chain A
        float u0x = a0x * wm0r - a1y * wm1i;
        float u0y = a0y * wm0r + a1x * wm1i;
        float u1x = a1x * wm0r - a0y * wm1i;
        float u1y = a1y * wm0r + a0x * wm1i;
        a0x = wt0r * u0x;   a0y = wt0r * u0y;
        a1x = -wt1i * u1y;  a1y = wt1i * u1x;      // (i wt1i)*u1

        // chain B (swap u0/u1 at v==1: t15 injection on mask bit 1)
        float v0x = b0x * wm0r - b1y * wm1i;
        float v0y = b0y * wm0r + b1x * wm1i;
        float v1x = b1x * wm0r - b0y * wm1i;
        float v1y = b1y * wm0r + b0x * wm1i;
        if (v == 1) {                               // compile-time after unroll
            float tx = v0x, ty = v0y;
            v0x = v1x; v0y = v1y; v1x = tx; v1y = ty;
        }
        b0x = wt0r * v0x;   b0y = wt0r * v0y;
        b1x = -wt1i * v1y;  b1y = wt1i * v1x;
    }

    // ---- close: mask bit 15 = t_14 ^ t15 ----
    float resAx, resBy;
    {
        const bool ae = (S >> 15) & 1;
        const float wm0r = ae ? cph[base + 15] : 1.f;
        const float wm1i = ae ? sph[base + 15] : 0.f;
        // chain A: (a0*wm(0) + a1*wm(1)).x
        resAx = a0x * wm0r - a1y * wm1i;
        // chain B: (b0*wm(1) + b1*wm(0)).y  (only .y needed: weight is i*w151i)
        resBy = b0x * wm1i + b1y * wm0r;
    }

    const bool ab15 = (S ^ (S >> 1) ^ (S >> 15)) & 1;   // b_15={0,1,15}
    const float w150r = ab15 ? cth[15] : 1.f;
    const float w151i = ab15 ? sth[15] : 0.f;

    out[b * NQ + w] = w150r * resAx - w151i * resBy;
}

extern "C" void kernel_launch(void* const* d_in, const int* in_sizes, int n_in,
                              void* d_out, int out_size) {
    const float* x   = (const float*)d_in[0];   // (32,16)
    const float* wts = (const float*)d_in[1];   // (2,16)
    if (n_in >= 2 && in_sizes[0] == 32 && in_sizes[1] == 512) {
        const float* tmp = x; x = wts; wts = tmp;  // defensive order swap
    }
    float* out = (float*)d_out;                 // (32,16) float32

    qnn_tm2<<<16, 32>>>(x, wts, out);
}

// round 4
// speedup vs baseline: 6.8271x; 1.0093x over previous
#include <cuda_runtime.h>

// 16-qubit, 2-layer BasicEntangler QNN — branchless transfer-matrix closed form.
// (Algebra verified rounds 1-3; see earlier derivation.)
//   <Z_{R_w}> = <0| Prod_{j in A} exp(i theta_j X_{m_j}) |0>
// reduced to a 2-state chain DP over wires, two parallel chains for t15=0/1.
// This round: __sincosf (SFU fast path), warp-local blocks (no block barrier),
// early independent loads. Pure latency optimization.

#define NQ 16

__constant__ unsigned int R_MASK[16] = {
    0xAAABu, 0xFFFDu, 0xFFFAu, 0xFFF5u, 0xFFEAu, 0xFFD5u, 0xFFAAu, 0xFF55u,
    0xFEAAu, 0xFD55u, 0xFAAAu, 0xF555u, 0xEAAAu, 0xD555u, 0xAAAAu, 0x5555u
};

__global__ void __launch_bounds__(32)
qnn_tm3(const float* __restrict__ x, const float* __restrict__ wts,
        float* __restrict__ out) {
    __shared__ float cph[32], sph[32], cth[NQ], sth[NQ];

    const int tid  = threadIdx.x;
    const int w    = tid & 15;                        // output wire
    const int b    = (blockIdx.x << 1) | (tid >> 4);  // sample
    const int base = tid & 16;                        // smem offset of my sample

    // issue all loads up front (independent latencies overlap)
    const float xv  = x[b * NQ + w];
    const float w0v = wts[w];
    const float w1v = wts[NQ + w];

    float s, c;
    __sincosf(xv + w0v, &s, &c);                      // phi = x + W0 (full angle)
    cph[tid] = c; sph[tid] = s;
    if (tid < NQ) {
        __sincosf(w1v, &s, &c);                       // layer-1 theta (full angle)
        cth[tid] = c; sth[tid] = s;
    }
    __syncwarp();                                     // block == warp

    const unsigned S = R_MASK[w];

    // chain A: t15 = 0; chain B: t15 = 1 (mask bits 0,1,15 get ^1)
    float a0x, a0y, a1x, a1y;
    float b0x, b0y, b1x, b1y;

    // ---- step w=0: amp_{t0} = wt(t0) * wm(t0 ^ t15) ----
    {
        const bool ab = (S ^ (S >> 1)) & 1;           // b_0={0,1} anticommutes?
        const bool ae = S & 1;
        const float wt0r = ab ? cth[0] : 1.f;
        const float wt1i = ab ? sth[0] : 0.f;
        const float wm0r = ae ? cph[base + 0] : 1.f;
        const float wm1i = ae ? sph[base + 0] : 0.f;
        a0x =  wt0r * wm0r;  a0y = 0.f;               // wt(0)*wm(0)
        a1x = -wt1i * wm1i;  a1y = 0.f;               // (i wt1i)*(i wm1i)
        b0x = 0.f;  b0y = wt0r * wm1i;                // wt(0)*wm(1)
        b1x = 0.f;  b1y = wt1i * wm0r;                // (i wt1i)*wm(0)
    }

    // ---- steps v=1..14: n_{tv} = wt(tv) * u_{tv [^1 if v==1 on chain B]}
    //      u_m = amp0*wm(m) + amp1*wm(1^m)
#pragma unroll
    for (int v = 1; v <= 14; v++) {
        const bool ab = ((S >> v) ^ (S >> (v + 1))) & 1;
        const bool ae = (S >> v) & 1;
        const float wt0r = ab ? cth[v] : 1.f;
        const float wt1i = ab ? sth[v] : 0.f;
        const float wm0r = ae ? cph[base + v] : 1.f;
        const float wm1i = ae ? sph[base + v] : 0.f;

        // chain A
        float u0x = a0x * wm0r - a1y * wm1i;
        float u0y = a0y * wm0r + a1x * wm1i;
        float u1x = a1x * wm0r - a0y * wm1i;
        float u1y = a1y * wm0r + a0x * wm1i;
        a0x = wt0r * u0x;   a0y = wt0r * u0y;
        a1x = -wt1i * u1y;  a1y = wt1i * u1x;         // (i wt1i)*u1

        // chain B (swap u0/u1 at v==1: t15 injection on mask bit 1)
        float v0x = b0x * wm0r - b1y * wm1i;
        float v0y = b0y * wm0r + b1x * wm1i;
        float v1x = b1x * wm0r - b0y * wm1i;
        float v1y = b1y * wm0r + b0x * wm1i;
        if (v == 1) {                                  // compile-time after unroll
            float tx = v0x, ty = v0y;
            v0x = v1x; v0y = v1y; v1x = tx; v1y = ty;
        }
        b0x = wt0r * v0x;   b0y = wt0r * v0y;
        b1x = -wt1i * v1y;  b1y = wt1i * v1x;
    }

    // ---- close: mask bit 15 = t_14 ^ t15 ----
    float resAx, resBy;
    {
        const bool ae = (S >> 15) & 1;
        const float wm0r = ae ? cph[base + 15] : 1.f;
        const float wm1i = ae ? sph[base + 15] : 0.f;
        // chain A: (a0*wm(0) + a1*wm(1)).x
        resAx = a0x * wm0r - a1y * wm1i;
        // chain B: (b0*wm(1) + b1*wm(0)).y
        resBy = b0x * wm1i + b1y * wm0r;
    }

    const bool ab15 = (S ^ (S >> 1) ^ (S >> 15)) & 1;  // b_15={0,1,15}
    const float w150r = ab15 ? cth[15] : 1.f;
    const float w151i = ab15 ? sth[15] : 0.f;

    out[b * NQ + w] = w150r * resAx - w151i * resBy;
}

extern "C" void kernel_launch(void* const* d_in, const int* in_sizes, int n_in,
                              void* d_out, int out_size) {
    const float* x   = (const float*)d_in[0];   // (32,16)
    const float* wts = (const float*)d_in[1];   // (2,16)
    if (n_in >= 2 && in_sizes[0] == 32 && in_sizes[1] == 512) {
        const float* tmp = x; x = wts; wts = tmp;  // defensive order swap
    }
    float* out = (float*)d_out;                 // (32,16) float32

    qnn_tm3<<<16, 32>>>(x, wts, out);
}

// round 5
// speedup vs baseline: 7.1618x; 1.0490x over previous
#include <cuda_runtime.h>

// 16-qubit, 2-layer BasicEntangler QNN — branchless transfer-matrix closed form.
// Algebra verified rounds 1-3:
//   <Z_{R_w}> = <0| Prod_j exp(i theta_j X_{m_j}) |0>  ->  2-state chain DP,
//   two chains (t15 = 0/1) combined as  w150r*valA - w151i*valB.
// This round: one chain per lane (lane^16 = partner chain), depth-2 recurrence
// via precomputed P = wt (x) wm products, parallel sincos prologue, shfl combine.

#define NQ 16

__constant__ unsigned int R_MASK[16] = {
    0xAAABu, 0xFFFDu, 0xFFFAu, 0xFFF5u, 0xFFEAu, 0xFFD5u, 0xFFAAu, 0xFF55u,
    0xFEAAu, 0xFD55u, 0xFAAAu, 0xF555u, 0xEAAAu, 0xD555u, 0xAAAAu, 0x5555u
};

__global__ void __launch_bounds__(32)
qnn_tm4(const float* __restrict__ x, const float* __restrict__ wts,
        float* __restrict__ out) {
    __shared__ float cph[NQ], sph[NQ], cth[NQ], sth[NQ];

    const int lane = threadIdx.x;
    const int w    = lane & 15;          // output wire
    const bool isB = lane >= 16;         // chain select (t15 = 1)
    const int b    = blockIdx.x;         // sample (one per block/warp)

    // prologue: halves of the warp compute phi- and theta-sincos in parallel
    if (!isB) {
        float s, c;
        __sincosf(x[b * NQ + w] + wts[w], &s, &c);   // phi = x + W0
        cph[w] = c; sph[w] = s;
    } else {
        float s, c;
        __sincosf(wts[NQ + w], &s, &c);              // layer-1 theta
        cth[w] = c; sth[w] = s;
    }
    __syncwarp();

    const unsigned S = R_MASK[w];

    // ---- init (step v=0), chain-B v==1 swap folded in as amp0<->amp1 ----
    float a0x, a0y, a1x, a1y;
    {
        const bool ab = (S ^ (S >> 1)) & 1;          // b_0={0,1}
        const bool ae = S & 1;
        const float wt0r = ab ? cth[0] : 1.f;
        const float wt1i = ab ? sth[0] : 0.f;
        const float wm0r = ae ? cph[0] : 1.f;
        const float wm1i = ae ? sph[0] : 0.f;
        const float q0 = (isB ? wt1i : wt0r) * wm0r;
        const float q1 = (isB ? wt0r : -wt1i) * wm1i;
        a0x = isB ? 0.f : q0;  a0y = isB ? q0 : 0.f;
        a1x = isB ? 0.f : q1;  a1y = isB ? q1 : 0.f;
    }

    // ---- steps v=1..14: depth-2 recurrence with precomputed products ----
#pragma unroll
    for (int v = 1; v <= 14; v++) {
        const bool ab = ((S >> v) ^ (S >> (v + 1))) & 1;
        const bool ae = (S >> v) & 1;
        const float wt0r = ab ? cth[v] : 1.f;
        const float wt1i = ab ? sth[v] : 0.f;
        const float wm0r = ae ? cph[v] : 1.f;
        const float wm1i = ae ? sph[v] : 0.f;
        const float P00 = wt0r * wm0r;
        const float P01 = wt0r * wm1i;
        const float P10 = wt1i * wm0r;
        const float P11 = wt1i * wm1i;
        const float n0x =  P00 * a0x - P01 * a1y;
        const float n0y =  P00 * a0y + P01 * a1x;
        const float n1x = -P10 * a1y - P11 * a0x;
        const float n1y =  P10 * a1x - P11 * a0y;
        a0x = n0x; a0y = n0y; a1x = n1x; a1y = n1y;
    }

    // ---- close (mask bit 15), per-chain component select ----
    float val;
    {
        const bool ae = (S >> 15) & 1;
        const float wm0r = ae ? cph[15] : 1.f;
        const float wm1i = ae ? sph[15] : 0.f;
        const float r0 = isB ? wm1i : wm0r;
        const float r1 = isB ? wm0r : -wm1i;
        val = a0x * r0 + a1y * r1;     // A: resAx ; B: resBy
    }

    // combine chains: lane<16 holds A, partner lane^16 holds B
    const float other = __shfl_xor_sync(0xFFFFFFFFu, val, 16);
    if (!isB) {
        const bool ab15 = (S ^ (S >> 1) ^ (S >> 15)) & 1;   // b_15={0,1,15}
        const float w150r = ab15 ? cth[15] : 1.f;
        const float w151i = ab15 ? sth[15] : 0.f;
        out[b * NQ + w] = w150r * val - w151i * other;
    }
}

extern "C" void kernel_launch(void* const* d_in, const int* in_sizes, int n_in,
                              void* d_out, int out_size) {
    const float* x   = (const float*)d_in[0];   // (32,16)
    const float* wts = (const float*)d_in[1];   // (2,16)
    if (n_in >= 2 && in_sizes[0] == 32 && in_sizes[1] == 512) {
        const float* tmp = x; x = wts; wts = tmp;  // defensive order swap
    }
    float* out = (float*)d_out;                 // (32,16) float32

    qnn_tm4<<<32, 32>>>(x, wts, out);
}